// round 13
// baseline (speedup 1.0000x reference)
#include <cuda_runtime.h>
#include <cuda_fp16.h>
#include <cstdint>

#define EPSF    1e-7f
#define MAXNORM (1.0f - 1e-5f)

// ---------------- W prep: f32 -> fp16, transposed to [k][n] ----------------
__device__ unsigned short g_WT[65536];   // [k][n] fp16

__global__ void wprep_kernel(const float* __restrict__ W) {
    __shared__ unsigned short sh[32][36];
    int bn0 = blockIdx.y * 32, bk0 = blockIdx.x * 32;
    int t = threadIdx.x;
    int r = t >> 3, c4 = (t & 7) * 4;
    float4 v = *reinterpret_cast<const float4*>(W + (bn0 + r) * 256 + bk0 + c4);
    float vv[4] = {v.x, v.y, v.z, v.w};
    #pragma unroll
    for (int j = 0; j < 4; ++j)
        sh[c4 + j][r] = __half_as_ushort(__float2half_rn(vv[j]));
    __syncthreads();
    unsigned short ho[4];
    #pragma unroll
    for (int j = 0; j < 4; ++j) ho[j] = sh[r][c4 + j];
    *reinterpret_cast<uint2*>(g_WT + (bk0 + r) * 256 + bn0 + c4) = *reinterpret_cast<uint2*>(ho);
}

// ---------------- PTX helpers ----------------
__device__ __forceinline__ uint32_t smem_u32(const void* p) {
    uint32_t a;
    asm("{ .reg .u64 t; cvta.to.shared.u64 t, %1; cvt.u32.u64 %0, t; }" : "=r"(a) : "l"(p));
    return a;
}
__device__ __forceinline__ void ldm_x4(uint32_t a, uint32_t& r0, uint32_t& r1, uint32_t& r2, uint32_t& r3) {
    asm volatile("ldmatrix.sync.aligned.m8n8.x4.shared.b16 {%0,%1,%2,%3}, [%4];"
                 : "=r"(r0), "=r"(r1), "=r"(r2), "=r"(r3) : "r"(a));
}
__device__ __forceinline__ void ldm_x4_t(uint32_t a, uint32_t& r0, uint32_t& r1, uint32_t& r2, uint32_t& r3) {
    asm volatile("ldmatrix.sync.aligned.m8n8.x4.trans.shared.b16 {%0,%1,%2,%3}, [%4];"
                 : "=r"(r0), "=r"(r1), "=r"(r2), "=r"(r3) : "r"(a));
}
__device__ __forceinline__ void mma16816(float* c, const uint32_t* a, const uint32_t* b) {
    asm volatile("mma.sync.aligned.m16n8k16.row.col.f32.f16.f16.f32 "
                 "{%0,%1,%2,%3}, {%4,%5,%6,%7}, {%8,%9}, {%0,%1,%2,%3};"
                 : "+f"(c[0]), "+f"(c[1]), "+f"(c[2]), "+f"(c[3])
                 : "r"(a[0]), "r"(a[1]), "r"(a[2]), "r"(a[3]), "r"(b[0]), "r"(b[1]));
}
__device__ __forceinline__ void cp16(uint32_t dst, const void* src) {
    asm volatile("cp.async.ca.shared.global [%0], [%1], 16;" :: "r"(dst), "l"(src) : "memory");
}
#define CP_COMMIT() asm volatile("cp.async.commit_group;" ::: "memory")
#define CP_WAIT3()  asm volatile("cp.async.wait_group 3;" ::: "memory")

__device__ __forceinline__ float dsmem_ld(uint32_t localAddr, uint32_t peerRank) {
    float v;
    asm volatile("{ .reg .b32 ra; mapa.shared::cluster.u32 ra, %1, %2; "
                 "ld.shared::cluster.f32 %0, [ra]; }"
                 : "=f"(v) : "r"(localAddr), "r"(peerRank));
    return v;
}
#define CLUSTER_ARRIVE() asm volatile("barrier.cluster.arrive.aligned;" ::: "memory")
#define CLUSTER_WAIT()   asm volatile("barrier.cluster.wait.aligned;" ::: "memory")

// ---------------- smem layout (per CTA: 128 rows x 128 cols) ----------------
#define RA_B    528            // A row stride (264 fp16) - conflict-free
#define RB_B    272            // B row stride (136 fp16) - 68 words ≡ 4 mod 32, conflict-free
#define OFF_A   0              // 128*528 = 67584
#define OFF_B   67584          // 4 stages x (32 * 272 = 8704) = 34816
#define BSTAGE  8704
#define OFF_BIAS 102400        // 256 f32 (full b)
#define OFF_RQ   103424        // 128 rows x 2 warps
#define OFF_RD   104448
#define OFF_RQS  105472        // 128 local row sums
#define OFF_RDS  105984
#define OFF_XN2  106496
#define OFF_G1   107008
#define OFF_G2   107520
#define OFF_BN2  108032
#define SMEM_TOTAL 108544

__global__ __launch_bounds__(128, 2) __cluster_dims__(2, 1, 1)
void hyp_f16_kernel(const float* __restrict__ x, const float* __restrict__ b,
                    float* __restrict__ out, int N)
{
    extern __shared__ char smem[];
    const uint32_t sb = smem_u32(smem);
    const int tid = threadIdx.x, lane = tid & 31, wid = tid >> 5;
    const int wm = wid >> 1, wn = wid & 1;        // 2x2 warp grid, tile 64x64
    uint32_t rank;
    asm("mov.u32 %0, %%cluster_ctarank;" : "=r"(rank));
    const int row0 = (blockIdx.x >> 1) * 128;
    const int ncol0 = (int)rank * 128;

    // ---- B k32-stage issue: CTA's 128-col half; 4 threads per k-row (64B each) ----
    auto issueB = [&](int kt, int s) {
        int r  = tid >> 2;                 // k-row 0..31
        int ci = tid & 3;                  // 64B chunk
        const unsigned short* src = g_WT + (kt * 32 + r) * 256 + ncol0 + ci * 32;
        uint32_t dst = sb + OFF_B + s * BSTAGE + r * RB_B + ci * 64;
        cp16(dst,      src);
        cp16(dst + 16, src + 8);
        cp16(dst + 32, src + 16);
        cp16(dst + 48, src + 24);
        CP_COMMIT();
    };
    issueB(0, 0);
    issueB(1, 1);
    issueB(2, 2);
    issueB(3, 3);

    // ---- bias -> smem (full 256) ----
    {
        float2 bv = *reinterpret_cast<const float2*>(b + tid * 2);
        *reinterpret_cast<float2*>(reinterpret_cast<float*>(smem + OFF_BIAS) + tid * 2) = bv;
    }

    // ---- x prologue: 1 thread per row, full 256 cols ----
    {
        int r = tid;
        int gr = row0 + r; if (gr >= N) gr = N - 1;
        const float* xp = x + (size_t)gr * 256;
        float xn2p = 0.f;
        #pragma unroll
        for (int i = 0; i < 32; ++i) {
            float4 v0 = *reinterpret_cast<const float4*>(xp + i * 8);
            float4 v1 = *reinterpret_cast<const float4*>(xp + i * 8 + 4);
            xn2p += v0.x*v0.x + v0.y*v0.y + v0.z*v0.z + v0.w*v0.w
                  + v1.x*v1.x + v1.y*v1.y + v1.z*v1.z + v1.w*v1.w;
            uint32_t p0, p1, p2, p3;
            asm("cvt.rn.f16x2.f32 %0, %1, %2;" : "=r"(p0) : "f"(v0.y), "f"(v0.x));
            asm("cvt.rn.f16x2.f32 %0, %1, %2;" : "=r"(p1) : "f"(v0.w), "f"(v0.z));
            asm("cvt.rn.f16x2.f32 %0, %1, %2;" : "=r"(p2) : "f"(v1.y), "f"(v1.x));
            asm("cvt.rn.f16x2.f32 %0, %1, %2;" : "=r"(p3) : "f"(v1.w), "f"(v1.z));
            uint32_t off = (uint32_t)r * RA_B + (uint32_t)(i * 8) * 2;
            *reinterpret_cast<uint4*>(smem + OFF_A + off) = make_uint4(p0, p1, p2, p3);
        }
        reinterpret_cast<float*>(smem + OFF_XN2)[r] = xn2p;
    }

    // ---- accumulators: warp tile 64x64 ----
    float acc[4][8][4];
    #pragma unroll
    for (int mm = 0; mm < 4; ++mm)
        #pragma unroll
        for (int nn = 0; nn < 8; ++nn)
            #pragma unroll
            for (int q = 0; q < 4; ++q) acc[mm][nn][q] = 0.f;

    const int arow  = lane & 15;
    const uint32_t akoff = (lane & 16) ? 16 : 0;
    const int bkrow = lane & 15;
    const uint32_t bnoff = (lane & 16) ? 16 : 0;

    const uint32_t aBase = sb + OFF_A + (uint32_t)(wm * 64 + arow) * RA_B + akoff;
    const uint32_t bColOff = (uint32_t)(wn * 64) * 2 + bnoff;

    // ---- main loop: 8 ktiles of k32 (2 x k16 steps), 4-stage pipeline (R8 rhythm) ----
    for (int kt = 0; kt < 8; ++kt) {
        CP_WAIT3();
        __syncthreads();
        const uint32_t bStage = sb + OFF_B + (uint32_t)(kt & 3) * BSTAGE
                              + (uint32_t)bkrow * RB_B + bColOff;

        #pragma unroll
        for (int ks = 0; ks < 2; ++ks) {
            const uint32_t kbA = (uint32_t)(kt * 64 + ks * 32);   // bytes
            const uint32_t kbB = (uint32_t)(ks * 16) * RB_B;

            uint32_t bh[8][2];
            #pragma unroll
            for (int nb = 0; nb < 4; ++nb)
                ldm_x4_t(bStage + kbB + (uint32_t)nb * 32,
                         bh[2*nb][0], bh[2*nb][1], bh[2*nb+1][0], bh[2*nb+1][1]);
            uint32_t ah[4][4];
            #pragma unroll
            for (int mm = 0; mm < 4; ++mm)
                ldm_x4(aBase + kbA + (uint32_t)mm * (16 * RA_B),
                       ah[mm][0], ah[mm][1], ah[mm][2], ah[mm][3]);

            #pragma unroll
            for (int mm = 0; mm < 4; ++mm)
                #pragma unroll
                for (int nn = 0; nn < 8; ++nn)
                    mma16816(acc[mm][nn], ah[mm], bh[nn]);
        }
        __syncthreads();
        if (kt < 4) issueB(kt + 4, kt & 3);
        else        CP_COMMIT();
    }

    // ---- epilogue: local per-row partial reductions over this CTA's 128 cols ----
    const float* bias = reinterpret_cast<const float*>(smem + OFF_BIAS);
    float bb[8][2];
    #pragma unroll
    for (int nn = 0; nn < 8; ++nn) {
        int col = ncol0 + wn * 64 + nn * 8 + (lane & 3) * 2;
        bb[nn][0] = bias[col];
        bb[nn][1] = bias[col + 1];
    }
    float* rq = reinterpret_cast<float*>(smem + OFF_RQ);
    float* rd = reinterpret_cast<float*>(smem + OFF_RD);

    #pragma unroll
    for (int mm = 0; mm < 4; ++mm)
        #pragma unroll
        for (int hf = 0; hf < 2; ++hf) {
            float q2 = 0.f, d = 0.f;
            #pragma unroll
            for (int nn = 0; nn < 8; ++nn) {
                float v0 = acc[mm][nn][hf * 2 + 0];
                float v1 = acc[mm][nn][hf * 2 + 1];
                q2 += v0 * v0 + v1 * v1;
                d  += v0 * bb[nn][0] + v1 * bb[nn][1];
            }
            q2 += __shfl_xor_sync(0xffffffffu, q2, 1);
            q2 += __shfl_xor_sync(0xffffffffu, q2, 2);
            d  += __shfl_xor_sync(0xffffffffu, d, 1);
            d  += __shfl_xor_sync(0xffffffffu, d, 2);
            if ((lane & 3) == 0) {
                int row = wm * 64 + mm * 16 + (lane >> 2) + hf * 8;
                rq[row * 2 + wn] = q2;
                rd[row * 2 + wn] = d;
            }
        }

    // ||b||^2 (full) once per CTA (warp 0)
    if (wid == 0) {
        float v = 0.f;
        #pragma unroll
        for (int i = 0; i < 8; ++i) {
            float bv = bias[lane + i * 32];
            v += bv * bv;
        }
        #pragma unroll
        for (int off = 16; off; off >>= 1) v += __shfl_xor_sync(0xffffffffu, v, off);
        if (lane == 0) *reinterpret_cast<float*>(smem + OFF_BN2) = v;
    }
    __syncthreads();

    // local row sums -> exchange buffers
    {
        int row = tid;
        reinterpret_cast<float*>(smem + OFF_RQS)[row] = rq[row * 2] + rq[row * 2 + 1];
        reinterpret_cast<float*>(smem + OFF_RDS)[row] = rd[row * 2] + rd[row * 2 + 1];
    }
    __syncthreads();

    // ---- cluster exchange of partials ----
    CLUSTER_ARRIVE();
    CLUSTER_WAIT();
    {
        uint32_t peer = rank ^ 1u;
        int row = tid;
        float q2 = reinterpret_cast<float*>(smem + OFF_RQS)[row]
                 + dsmem_ld(sb + OFF_RQS + row * 4, peer);
        float d  = reinterpret_cast<float*>(smem + OFF_RDS)[row]
                 + dsmem_ld(sb + OFF_RDS + row * 4, peer);
        float xn2 = reinterpret_cast<float*>(smem + OFF_XN2)[row];
        float bn2 = *reinterpret_cast<float*>(smem + OFF_BN2);
        float bn  = sqrtf(bn2);

        float xn  = fmaxf(sqrtf(xn2), EPSF);
        float u   = fminf(xn, 1.0f - 1e-7f);
        float at  = 0.5f * (log1pf(u) - log1pf(-u));
        float mxn = fmaxf(sqrtf(q2), EPSF);
        float t   = tanhf(mxn / xn * at);
        t = fminf(t, MAXNORM);
        float alpha = t / mxn;
        float s  = 1.0f - t * t;
        float vn = fmaxf(s * bn, EPSF);
        float lam = 2.0f / fmaxf(s, EPSF);
        float beta = tanhf(0.5f * lam * vn) * s / vn;
        float xy = alpha * beta * d;
        float y2 = beta * beta * bn2;
        float A   = 1.0f + 2.0f * xy + y2;
        float den = fmaxf(1.0f + 2.0f * xy + (t * t) * y2, EPSF);
        float g1 = A * alpha / den;
        float g2 = s * beta  / den;
        float o2 = g1 * g1 * q2 + 2.0f * g1 * g2 * d + g2 * g2 * bn2;
        float on = fmaxf(sqrtf(o2), EPSF);
        if (on > MAXNORM) { float f = MAXNORM / on; g1 *= f; g2 *= f; }
        reinterpret_cast<float*>(smem + OFF_G1)[row] = g1;
        reinterpret_cast<float*>(smem + OFF_G2)[row] = g2;
    }
    __syncthreads();

    // ---- scaled store (this CTA's 128 cols) ----
    const float* g1s = reinterpret_cast<const float*>(smem + OFF_G1);
    const float* g2s = reinterpret_cast<const float*>(smem + OFF_G2);
    #pragma unroll
    for (int mm = 0; mm < 4; ++mm)
        #pragma unroll
        for (int hf = 0; hf < 2; ++hf) {
            int row = wm * 64 + mm * 16 + (lane >> 2) + hf * 8;
            float g1 = g1s[row], g2 = g2s[row];
            int grow = row0 + row;
            if (grow < N) {
                float* orow = out + (size_t)grow * 256;
                #pragma unroll
                for (int nn = 0; nn < 8; ++nn) {
                    float2 v;
                    v.x = g1 * acc[mm][nn][hf * 2 + 0] + g2 * bb[nn][0];
                    v.y = g1 * acc[mm][nn][hf * 2 + 1] + g2 * bb[nn][1];
                    *reinterpret_cast<float2*>(orow + ncol0 + wn * 64 + nn * 8 + (lane & 3) * 2) = v;
                }
            }
        }

    // ensure peer has finished reading our RQS/RDS before smem is released
    CLUSTER_ARRIVE();
    CLUSTER_WAIT();
}

extern "C" void kernel_launch(void* const* d_in, const int* in_sizes, int n_in,
                              void* d_out, int out_size) {
    const float* x = (const float*)d_in[0];
    const float* W = (const float*)d_in[1];
    const float* b = (const float*)d_in[2];
    float* out = (float*)d_out;
    int N = in_sizes[0] / 256;

    cudaFuncSetAttribute(hyp_f16_kernel, cudaFuncAttributeMaxDynamicSharedMemorySize, SMEM_TOTAL);

    dim3 wgrid(8, 8);
    wprep_kernel<<<wgrid, 256>>>(W);
    int grid = ((N + 127) / 128) * 2;
    hyp_f16_kernel<<<grid, 128, SMEM_TOTAL>>>(x, b, out, N);
}

// round 14
// speedup vs baseline: 1.3083x; 1.3083x over previous
#include <cuda_runtime.h>
#include <cuda_fp16.h>
#include <cstdint>

#define EPSF    1e-7f
#define MAXNORM (1.0f - 1e-5f)

// ---------------- W prep: f32 -> fp16, transposed to [k][n] ----------------
__device__ unsigned short g_WT[65536];   // [k][n] fp16

__global__ void wprep_kernel(const float* __restrict__ W) {
    __shared__ unsigned short sh[32][36];
    int bn0 = blockIdx.y * 32, bk0 = blockIdx.x * 32;
    int t = threadIdx.x;
    int r = t >> 3, c4 = (t & 7) * 4;
    float4 v = *reinterpret_cast<const float4*>(W + (bn0 + r) * 256 + bk0 + c4);
    float vv[4] = {v.x, v.y, v.z, v.w};
    #pragma unroll
    for (int j = 0; j < 4; ++j)
        sh[c4 + j][r] = __half_as_ushort(__float2half_rn(vv[j]));
    __syncthreads();
    unsigned short ho[4];
    #pragma unroll
    for (int j = 0; j < 4; ++j) ho[j] = sh[r][c4 + j];
    *reinterpret_cast<uint2*>(g_WT + (bk0 + r) * 256 + bn0 + c4) = *reinterpret_cast<uint2*>(ho);
}

// ---------------- PTX helpers ----------------
__device__ __forceinline__ uint32_t smem_u32(const void* p) {
    uint32_t a;
    asm("{ .reg .u64 t; cvta.to.shared.u64 t, %1; cvt.u32.u64 %0, t; }" : "=r"(a) : "l"(p));
    return a;
}
__device__ __forceinline__ void ldm_x4(uint32_t a, uint32_t& r0, uint32_t& r1, uint32_t& r2, uint32_t& r3) {
    asm volatile("ldmatrix.sync.aligned.m8n8.x4.shared.b16 {%0,%1,%2,%3}, [%4];"
                 : "=r"(r0), "=r"(r1), "=r"(r2), "=r"(r3) : "r"(a));
}
__device__ __forceinline__ void ldm_x4_t(uint32_t a, uint32_t& r0, uint32_t& r1, uint32_t& r2, uint32_t& r3) {
    asm volatile("ldmatrix.sync.aligned.m8n8.x4.trans.shared.b16 {%0,%1,%2,%3}, [%4];"
                 : "=r"(r0), "=r"(r1), "=r"(r2), "=r"(r3) : "r"(a));
}
__device__ __forceinline__ void mma16816(float* c, const uint32_t* a, const uint32_t* b) {
    asm volatile("mma.sync.aligned.m16n8k16.row.col.f32.f16.f16.f32 "
                 "{%0,%1,%2,%3}, {%4,%5,%6,%7}, {%8,%9}, {%0,%1,%2,%3};"
                 : "+f"(c[0]), "+f"(c[1]), "+f"(c[2]), "+f"(c[3])
                 : "r"(a[0]), "r"(a[1]), "r"(a[2]), "r"(a[3]), "r"(b[0]), "r"(b[1]));
}
__device__ __forceinline__ void cp16(uint32_t dst, const void* src) {
    asm volatile("cp.async.ca.shared.global [%0], [%1], 16;" :: "r"(dst), "l"(src) : "memory");
}
#define CP_COMMIT() asm volatile("cp.async.commit_group;" ::: "memory")
#define CP_WAIT3()  asm volatile("cp.async.wait_group 3;" ::: "memory")

// ---------------- smem layout (per 128-row CTA) ----------------
#define RA_B    528            // row stride bytes (264 fp16) - ldmatrix conflict-free
#define OFF_A   0              // 128 * 528 = 67584
#define OFF_B   67584          // 4 stages x (32 k-rows * 528B = 16896) = 67584
#define BSTAGE  16896
#define OFF_BIAS 135168
#define OFF_RQ   136192
#define OFF_RD   138240
#define OFF_XN2  140288
#define OFF_G1   140800
#define OFF_G2   141312
#define OFF_BN2  141824
#define SMEM_TOTAL 142336

__global__ __launch_bounds__(256, 1)
void hyp_f16_kernel(const float* __restrict__ x, const float* __restrict__ b,
                    float* __restrict__ out, int N)
{
    extern __shared__ char smem[];
    const uint32_t sb = smem_u32(smem);
    const int tid = threadIdx.x, lane = tid & 31, wid = tid >> 5;
    const int wm = wid >> 2, wn = wid & 3;        // 2x4 warp grid, tile 64x64
    const int row0 = blockIdx.x * 128;

    // ---- B k32-stage issue: 256 threads, 8 threads per k-row (64B each) ----
    auto issueB = [&](int kt, int s) {
        int r  = tid >> 3;                 // k-row 0..31
        int ci = tid & 7;                  // 64B chunk
        const unsigned short* src = g_WT + (kt * 32 + r) * 256 + ci * 32;
        uint32_t dst = sb + OFF_B + s * BSTAGE + r * RA_B + ci * 64;
        cp16(dst,      src);
        cp16(dst + 16, src + 8);
        cp16(dst + 32, src + 16);
        cp16(dst + 48, src + 24);
        CP_COMMIT();
    };
    issueB(0, 0);
    issueB(1, 1);
    issueB(2, 2);

    // ---- bias -> smem ----
    reinterpret_cast<float*>(smem + OFF_BIAS)[tid] = b[tid];

    // ---- x prologue: 2 threads per row, 128 cols each; rotated chunk order ----
    {
        int r = tid >> 1;
        int h = tid & 1;
        int gr = row0 + r; if (gr >= N) gr = N - 1;
        const float* xp = x + (size_t)gr * 256 + h * 128;
        float xn2p = 0.f;
        #pragma unroll
        for (int j = 0; j < 16; ++j) {
            int i = (j + 4 * h) & 15;          // chunk rotation
            float4 v0 = *reinterpret_cast<const float4*>(xp + i * 8);
            float4 v1 = *reinterpret_cast<const float4*>(xp + i * 8 + 4);
            xn2p += v0.x*v0.x + v0.y*v0.y + v0.z*v0.z + v0.w*v0.w
                  + v1.x*v1.x + v1.y*v1.y + v1.z*v1.z + v1.w*v1.w;
            uint32_t p0, p1, p2, p3;
            asm("cvt.rn.f16x2.f32 %0, %1, %2;" : "=r"(p0) : "f"(v0.y), "f"(v0.x));
            asm("cvt.rn.f16x2.f32 %0, %1, %2;" : "=r"(p1) : "f"(v0.w), "f"(v0.z));
            asm("cvt.rn.f16x2.f32 %0, %1, %2;" : "=r"(p2) : "f"(v1.y), "f"(v1.x));
            asm("cvt.rn.f16x2.f32 %0, %1, %2;" : "=r"(p3) : "f"(v1.w), "f"(v1.z));
            uint32_t off = (uint32_t)r * RA_B + (uint32_t)(h * 128 + i * 8) * 2;
            *reinterpret_cast<uint4*>(smem + OFF_A + off) = make_uint4(p0, p1, p2, p3);
        }
        xn2p += __shfl_xor_sync(0xffffffffu, xn2p, 1);
        if (!(tid & 1)) reinterpret_cast<float*>(smem + OFF_XN2)[r] = xn2p;
    }

    // ---- accumulators: warp tile 64x64 ----
    float acc[4][8][4];
    #pragma unroll
    for (int mm = 0; mm < 4; ++mm)
        #pragma unroll
        for (int nn = 0; nn < 8; ++nn)
            #pragma unroll
            for (int q = 0; q < 4; ++q) acc[mm][nn][q] = 0.f;

    const int arow  = lane & 15;
    const uint32_t akoff = (lane & 16) ? 16 : 0;
    const int bkrow = lane & 15;
    const uint32_t bnoff = (lane & 16) ? 16 : 0;

    const uint32_t aBase = sb + OFF_A + (uint32_t)(wm * 64 + arow) * RA_B + akoff;
    const uint32_t bColOff = (uint32_t)(wn * 64) * 2 + bnoff;

    // ---- main loop: 8 ktiles of k32, 4 slots, ONE barrier per ktile.
    //      Order per kt: wait3 (own stage-kt groups done) -> syncthreads
    //      (all threads' stage-kt data visible AND slot (kt+3)&3 drained,
    //       since it was last read in iteration kt-1) -> issue stage kt+3. ----
    for (int kt = 0; kt < 8; ++kt) {
        CP_WAIT3();
        __syncthreads();
        if (kt < 5) issueB(kt + 3, (kt + 3) & 3);
        else        CP_COMMIT();           // keep wait_group accounting exact

        const uint32_t bStage = sb + OFF_B + (uint32_t)(kt & 3) * BSTAGE
                              + (uint32_t)bkrow * RA_B + bColOff;

        #pragma unroll
        for (int ks = 0; ks < 2; ++ks) {
            const uint32_t kbA = (uint32_t)(kt * 64 + ks * 32);   // bytes
            const uint32_t kbB = (uint32_t)(ks * 16) * RA_B;

            uint32_t bh[8][2];
            #pragma unroll
            for (int nb = 0; nb < 4; ++nb)
                ldm_x4_t(bStage + kbB + (uint32_t)nb * 32,
                         bh[2*nb][0], bh[2*nb][1], bh[2*nb+1][0], bh[2*nb+1][1]);
            uint32_t ah[4][4];
            #pragma unroll
            for (int mm = 0; mm < 4; ++mm)
                ldm_x4(aBase + kbA + (uint32_t)mm * (16 * RA_B),
                       ah[mm][0], ah[mm][1], ah[mm][2], ah[mm][3]);

            #pragma unroll
            for (int mm = 0; mm < 4; ++mm)
                #pragma unroll
                for (int nn = 0; nn < 8; ++nn)
                    mma16816(acc[mm][nn], ah[mm], bh[nn]);
        }
    }

    // ---- epilogue: per-row reductions ----
    __syncthreads();
    const float* bias = reinterpret_cast<const float*>(smem + OFF_BIAS);
    float bb[8][2];
    #pragma unroll
    for (int nn = 0; nn < 8; ++nn) {
        int col = wn * 64 + nn * 8 + (lane & 3) * 2;
        bb[nn][0] = bias[col];
        bb[nn][1] = bias[col + 1];
    }
    float* rq = reinterpret_cast<float*>(smem + OFF_RQ);
    float* rd = reinterpret_cast<float*>(smem + OFF_RD);

    #pragma unroll
    for (int mm = 0; mm < 4; ++mm)
        #pragma unroll
        for (int hf = 0; hf < 2; ++hf) {
            float q2 = 0.f, d = 0.f;
            #pragma unroll
            for (int nn = 0; nn < 8; ++nn) {
                float v0 = acc[mm][nn][hf * 2 + 0];
                float v1 = acc[mm][nn][hf * 2 + 1];
                q2 += v0 * v0 + v1 * v1;
                d  += v0 * bb[nn][0] + v1 * bb[nn][1];
            }
            q2 += __shfl_xor_sync(0xffffffffu, q2, 1);
            q2 += __shfl_xor_sync(0xffffffffu, q2, 2);
            d  += __shfl_xor_sync(0xffffffffu, d, 1);
            d  += __shfl_xor_sync(0xffffffffu, d, 2);
            if ((lane & 3) == 0) {
                int row = wm * 64 + mm * 16 + (lane >> 2) + hf * 8;
                rq[row * 4 + wn] = q2;
                rd[row * 4 + wn] = d;
            }
        }

    // ||b||^2 once per CTA (warp 0)
    if (wid == 0) {
        float v = 0.f;
        #pragma unroll
        for (int i = 0; i < 8; ++i) {
            float bv = bias[lane + i * 32];
            v += bv * bv;
        }
        #pragma unroll
        for (int off = 16; off; off >>= 1) v += __shfl_xor_sync(0xffffffffu, v, off);
        if (lane == 0) *reinterpret_cast<float*>(smem + OFF_BN2) = v;
    }
    __syncthreads();

    // ---- per-row scalar chain ----
    if (tid < 128) {
        int row = tid;
        float q2 = rq[row*4+0] + rq[row*4+1] + rq[row*4+2] + rq[row*4+3];
        float d  = rd[row*4+0] + rd[row*4+1] + rd[row*4+2] + rd[row*4+3];
        float xn2 = reinterpret_cast<float*>(smem + OFF_XN2)[row];
        float bn2 = *reinterpret_cast<float*>(smem + OFF_BN2);
        float bn  = sqrtf(bn2);

        float xn  = fmaxf(sqrtf(xn2), EPSF);
        float u   = fminf(xn, 1.0f - 1e-7f);
        float at  = 0.5f * (log1pf(u) - log1pf(-u));
        float mxn = fmaxf(sqrtf(q2), EPSF);
        float t   = tanhf(mxn / xn * at);
        t = fminf(t, MAXNORM);
        float alpha = t / mxn;
        float s  = 1.0f - t * t;
        float vn = fmaxf(s * bn, EPSF);
        float lam = 2.0f / fmaxf(s, EPSF);
        float beta = tanhf(0.5f * lam * vn) * s / vn;
        float xy = alpha * beta * d;
        float y2 = beta * beta * bn2;
        float A   = 1.0f + 2.0f * xy + y2;
        float den = fmaxf(1.0f + 2.0f * xy + (t * t) * y2, EPSF);
        float g1 = A * alpha / den;
        float g2 = s * beta  / den;
        float o2 = g1 * g1 * q2 + 2.0f * g1 * g2 * d + g2 * g2 * bn2;
        float on = fmaxf(sqrtf(o2), EPSF);
        if (on > MAXNORM) { float f = MAXNORM / on; g1 *= f; g2 *= f; }
        reinterpret_cast<float*>(smem + OFF_G1)[row] = g1;
        reinterpret_cast<float*>(smem + OFF_G2)[row] = g2;
    }
    __syncthreads();

    // ---- scaled store ----
    const float* g1s = reinterpret_cast<const float*>(smem + OFF_G1);
    const float* g2s = reinterpret_cast<const float*>(smem + OFF_G2);
    #pragma unroll
    for (int mm = 0; mm < 4; ++mm)
        #pragma unroll
        for (int hf = 0; hf < 2; ++hf) {
            int row = wm * 64 + mm * 16 + (lane >> 2) + hf * 8;
            float g1 = g1s[row], g2 = g2s[row];
            int grow = row0 + row;
            if (grow < N) {
                float* orow = out + (size_t)grow * 256;
                #pragma unroll
                for (int nn = 0; nn < 8; ++nn) {
                    float2 v;
                    v.x = g1 * acc[mm][nn][hf * 2 + 0] + g2 * bb[nn][0];
                    v.y = g1 * acc[mm][nn][hf * 2 + 1] + g2 * bb[nn][1];
                    *reinterpret_cast<float2*>(orow + wn * 64 + nn * 8 + (lane & 3) * 2) = v;
                }
            }
        }
}

extern "C" void kernel_launch(void* const* d_in, const int* in_sizes, int n_in,
                              void* d_out, int out_size) {
    const float* x = (const float*)d_in[0];
    const float* W = (const float*)d_in[1];
    const float* b = (const float*)d_in[2];
    float* out = (float*)d_out;
    int N = in_sizes[0] / 256;

    cudaFuncSetAttribute(hyp_f16_kernel, cudaFuncAttributeMaxDynamicSharedMemorySize, SMEM_TOTAL);

    dim3 wgrid(8, 8);
    wprep_kernel<<<wgrid, 256>>>(W);
    int grid = (N + 127) / 128;
    hyp_f16_kernel<<<grid, 256, SMEM_TOTAL>>>(x, b, out, N);
}